// round 2
// baseline (speedup 1.0000x reference)
#include <cuda_runtime.h>
#include <math.h>

#define BSZ 4
#define NQ  1024
#define NB  8
#define DD  64
#define MM  2048
#define CC  64
#define SBT (BSZ*NB)
#define NEGV (-1.0e9f)
#define EPSV 1e-8f
#define SMAXV 4.0f
#define BUDGETV 512.0f
#define FINF __int_as_float(0x7f800000)

// ---------- device scratch (no allocation allowed) ----------
__device__ float g_nov[SBT*NQ];
__device__ float g_cand_val[SBT*CC];
__device__ int   g_cand_idx[SBT*CC];
__device__ float g_coef[SBT*CC];
__device__ float g_ckn[SBT*CC*DD];
__device__ float g_cvv[SBT*CC*DD];
__device__ float g_Z[SBT*CC*MM];   // alpha, layout [sb][c][m]
__device__ float g_aps[SBT*MM];
__device__ float g_tot[SBT];

__device__ __forceinline__ void ins16(float* tv, int* ti, float v, int m) {
    if (v <= tv[0]) return;
    tv[0] = v; ti[0] = m;
#pragma unroll
    for (int i = 0; i < 15; ++i) {
        if (tv[i] > tv[i+1]) {
            float tf = tv[i]; tv[i] = tv[i+1]; tv[i+1] = tf;
            int   tx = ti[i]; ti[i] = ti[i+1]; ti[i+1] = tx;
        }
    }
}

// merge lane-sorted top16 -> global top16, softmax + V gather fused
__device__ __forceinline__ void merge_out(float* tv, int* ti, const float* Vb,
                                          int lane, float& o0, float& o1) {
    float vmax0 = 0.f, wsum = 0.f;
    o0 = 0.f; o1 = 0.f;
#pragma unroll 1
    for (int r = 0; r < 16; ++r) {
        unsigned u = __float_as_uint(tv[15]);
        u = (u & 0x80000000u) ? ~u : (u | 0x80000000u);
        unsigned long long key = ((unsigned long long)u << 32) | (unsigned)(31 - lane);
#pragma unroll
        for (int o = 16; o; o >>= 1) {
            unsigned long long k2 = __shfl_xor_sync(0xffffffffu, key, o);
            if (k2 > key) key = k2;
        }
        int wl = 31 - (int)(key & 31u);
        unsigned uu = (unsigned)(key >> 32);
        float v = (uu & 0x80000000u) ? __uint_as_float(uu ^ 0x80000000u)
                                     : __uint_as_float(~uu);
        int mi = __shfl_sync(0xffffffffu, ti[15], wl);
        if (r == 0) vmax0 = v;
        float e = __expf(v - vmax0);
        wsum += e;
        o0 += e * Vb[mi*DD + lane];
        o1 += e * Vb[mi*DD + lane + 32];
        if (lane == wl) {
#pragma unroll
            for (int i = 15; i > 0; --i) { tv[i] = tv[i-1]; ti[i] = ti[i-1]; }
            tv[0] = -FINF;
        }
    }
    float inv = 1.f / wsum;
    o0 *= inv; o1 *= inv;
}

// ============ kA: read attention + novelty ============
__global__ __launch_bounds__(512, 1) void kA(
    const float* __restrict__ q, const float* __restrict__ qn_,
    const float* __restrict__ surprise, const float* __restrict__ wnov,
    const float* __restrict__ emK, const float* __restrict__ emV,
    const float* __restrict__ emS, float* __restrict__ out)
{
    const int s = blockIdx.z, b = blockIdx.y, qt = blockIdx.x;
    const int sb = s*NB + b;
    const int tid = threadIdx.x, w = tid >> 5, lane = tid & 31;

    __shared__ float Ksm[64][68];
    __shared__ float Qs[32][64];
    __shared__ float Qn[32][64];
    __shared__ float actv[64];

    const int n0 = qt * 32;
    {
        int r = tid >> 4, c4 = (tid & 15) << 2;
        int off = ((s*NQ + n0 + r)*NB + b)*DD + c4;
        *(float4*)&Qs[r][c4] = *(const float4*)&q[off];
        *(float4*)&Qn[r][c4] = *(const float4*)&qn_[off];
    }

    float tv0[16], tv1[16]; int ti0[16], ti1[16];
#pragma unroll
    for (int i = 0; i < 16; ++i) { tv0[i]=-FINF; tv1[i]=-FINF; ti0[i]=0; ti1[i]=0; }
    float mx0 = -1.0f, mx1 = -1.0f;
    const int q0 = 2*w, q1 = 2*w + 1;
    const float* Kb = emK + sb*MM*DD;
    const float* Sb = emS + sb*MM;

    for (int t = 0; t < MM/64; ++t) {
        __syncthreads();
        for (int i = tid; i < 1024; i += 512) {
            int r = i >> 4, c4 = (i & 15) << 2;
            *(float4*)&Ksm[r][c4] = *(const float4*)&Kb[(t*64 + r)*DD + c4];
        }
        if (tid < 64) actv[tid] = Sb[t*64 + tid];
        __syncthreads();
#pragma unroll
        for (int mo = 0; mo < 64; mo += 32) {
            const int ml = mo + lane;
            float a00=0.f, a01=0.f, a10=0.f, a11=0.f;
#pragma unroll
            for (int d4 = 0; d4 < 64; d4 += 4) {
                float4 kk = *(float4*)&Ksm[ml][d4];
                float4 x0 = *(float4*)&Qs[q0][d4];
                float4 y0 = *(float4*)&Qn[q0][d4];
                float4 x1 = *(float4*)&Qs[q1][d4];
                float4 y1 = *(float4*)&Qn[q1][d4];
                a00 += x0.x*kk.x + x0.y*kk.y + x0.z*kk.z + x0.w*kk.w;
                a01 += y0.x*kk.x + y0.y*kk.y + y0.z*kk.z + y0.w*kk.w;
                a10 += x1.x*kk.x + x1.y*kk.y + x1.z*kk.z + x1.w*kk.w;
                a11 += y1.x*kk.x + y1.y*kk.y + y1.z*kk.z + y1.w*kk.w;
            }
            const bool act = actv[ml] > 0.f;
            const int gm = t*64 + ml;
            float sc0 = act ? a00 : NEGV;
            float sm0 = act ? a01 : -1.0f;
            float sc1 = act ? a10 : NEGV;
            float sm1 = act ? a11 : -1.0f;
            mx0 = fmaxf(mx0, sm0);
            mx1 = fmaxf(mx1, sm1);
            ins16(tv0, ti0, sc0, gm);
            ins16(tv1, ti1, sc1, gm);
        }
    }

    const float* Vb = emV + sb*MM*DD;
    float o00, o01, o10, o11;
    merge_out(tv0, ti0, Vb, lane, o00, o01);
    merge_out(tv1, ti1, Vb, lane, o10, o11);

    int ob0 = ((s*NQ + n0 + q0)*NB + b)*DD;
    int ob1 = ((s*NQ + n0 + q1)*NB + b)*DD;
    out[ob0 + lane] = o00; out[ob0 + lane + 32] = o01;
    out[ob1 + lane] = o10; out[ob1 + lane + 32] = o11;

#pragma unroll
    for (int o = 16; o; o >>= 1) {
        mx0 = fmaxf(mx0, __shfl_xor_sync(0xffffffffu, mx0, o));
        mx1 = fmaxf(mx1, __shfl_xor_sync(0xffffffffu, mx1, o));
    }
    if (lane == 0) {
        float ms0 = fmaxf(mx0, 0.f), ms1 = fmaxf(mx1, 0.f);
        int off0 = (s*NQ + n0 + q0)*NB + b;
        int off1 = (s*NQ + n0 + q1)*NB + b;
        float w0 = wnov[off0], w1 = wnov[off1];
        g_nov[sb*NQ + n0 + q0] = w0*surprise[off0] + (1.f-w0)*(1.f-ms0);
        g_nov[sb*NQ + n0 + q1] = w1*surprise[off1] + (1.f-w1)*(1.f-ms1);
    }
}

// ============ kB: top-64 novelty per (s,b), coef ============
__global__ void kB(const float* __restrict__ g_em_in)
{
    const int sb = blockIdx.x, tid = threadIdx.x;
    __shared__ float vals[NQ];
    __shared__ float rv[8]; __shared__ int ri[8];
    __shared__ float svals[CC];
    __shared__ float ssum;
    for (int i = tid; i < NQ; i += 256) vals[i] = g_nov[sb*NQ + i];
    __syncthreads();
    for (int r = 0; r < CC; ++r) {
        float bv = -FINF; int bi = 0;
        for (int i = tid; i < NQ; i += 256) {
            float v = vals[i];
            if (v > bv) { bv = v; bi = i; }
        }
#pragma unroll
        for (int o = 16; o; o >>= 1) {
            float v2 = __shfl_xor_sync(0xffffffffu, bv, o);
            int   i2 = __shfl_xor_sync(0xffffffffu, bi, o);
            if (v2 > bv || (v2 == bv && i2 < bi)) { bv = v2; bi = i2; }
        }
        if ((tid & 31) == 0) { rv[tid>>5] = bv; ri[tid>>5] = bi; }
        __syncthreads();
        if (tid == 0) {
            for (int k = 1; k < 8; ++k)
                if (rv[k] > bv || (rv[k] == bv && ri[k] < bi)) { bv = rv[k]; bi = ri[k]; }
            g_cand_val[sb*CC + r] = bv;
            g_cand_idx[sb*CC + r] = bi;
            svals[r] = bv;
            vals[bi] = -FINF;
        }
        __syncthreads();
    }
    if (tid == 0) {
        float s = 0.f;
        for (int c = 0; c < CC; ++c) s += svals[c];
        ssum = s;
    }
    __syncthreads();
    if (tid < CC)
        g_coef[sb*CC + tid] = g_em_in[sb] * svals[tid] / (ssum + EPSV);
}

// ============ kC: gather candidates, unit-normalize K ============
__global__ void kC(const float* __restrict__ qn_, const float* __restrict__ vn_)
{
    const int c = blockIdx.x, sb = blockIdx.y;
    const int s = sb >> 3, b = sb & 7;
    const int lane = threadIdx.x;
    const int idx = g_cand_idx[sb*CC + c];
    const int base = ((s*NQ + idx)*NB + b)*DD;
    float k0 = qn_[base + lane], k1 = qn_[base + lane + 32];
    float v0 = vn_[base + lane], v1 = vn_[base + lane + 32];
    float nsq = k0*k0 + k1*k1;
#pragma unroll
    for (int o = 16; o; o >>= 1) nsq += __shfl_xor_sync(0xffffffffu, nsq, o);
    float nrm = fmaxf(sqrtf(nsq), EPSV);
    int ob = (sb*CC + c)*DD;
    g_ckn[ob + lane]      = k0/nrm;
    g_ckn[ob + lane + 32] = k1/nrm;
    g_cvv[ob + lane]      = v0;
    g_cvv[ob + lane + 32] = v1;
}

// ============ kD1: slot scores -> Z raw ============
__global__ __launch_bounds__(256) void kD1(
    const float* __restrict__ emK, const float* __restrict__ emS,
    const float* __restrict__ ww, const float* __restrict__ tau)
{
    const int sb = blockIdx.y;
    const int m = blockIdx.x*256 + threadIdx.x;
    __shared__ float ckns[CC][68];
    for (int i = threadIdx.x; i < 1024; i += 256) {
        int c = i >> 4, d4 = (i & 15) << 2;
        *(float4*)&ckns[c][d4] = *(const float4*)&g_ckn[(sb*CC + c)*DD + d4];
    }
    __syncthreads();
    float kreg[DD];
    const float* Kr = emK + (size_t)(sb*MM + m)*DD;
#pragma unroll
    for (int d4 = 0; d4 < DD; d4 += 4) *(float4*)&kreg[d4] = *(const float4*)&Kr[d4];
    const float bias = -ww[sb]*emS[sb*MM + m];
    const float invtau = 1.f / fmaxf(tau[sb], 0.01f);
    float* Zb = g_Z + (size_t)sb*CC*MM + m;
#pragma unroll 4
    for (int c = 0; c < CC; ++c) {
        float acc = 0.f;
#pragma unroll
        for (int d4 = 0; d4 < DD; d4 += 4) {
            float4 ck = *(float4*)&ckns[c][d4];
            acc += ck.x*kreg[d4] + ck.y*kreg[d4+1] + ck.z*kreg[d4+2] + ck.w*kreg[d4+3];
        }
        Zb[(size_t)c*MM] = (acc + bias) * invtau;
    }
}

// ============ kD2: softmax over m per (sb,c), scale by coef ============
__global__ __launch_bounds__(256) void kD2()
{
    const int row = blockIdx.x;          // sb*CC + c
    const int tid = threadIdx.x;
    float* zr = g_Z + (size_t)row*MM;
    __shared__ float buf[MM];
    __shared__ float red[256];
    float mx = -FINF;
    for (int j = tid; j < MM; j += 256) { float v = zr[j]; buf[j] = v; mx = fmaxf(mx, v); }
    red[tid] = mx; __syncthreads();
    for (int s2 = 128; s2; s2 >>= 1) { if (tid < s2) red[tid] = fmaxf(red[tid], red[tid+s2]); __syncthreads(); }
    mx = red[0]; __syncthreads();
    float sm = 0.f;
    for (int j = tid; j < MM; j += 256) { float e = __expf(buf[j] - mx); buf[j] = e; sm += e; }
    red[tid] = sm; __syncthreads();
    for (int s2 = 128; s2; s2 >>= 1) { if (tid < s2) red[tid] += red[tid+s2]; __syncthreads(); }
    const float scale = g_coef[row] / red[0];
    for (int j = tid; j < MM; j += 256) zr[j] = buf[j] * scale;
}

// ============ kD3: alpha_per_slot ============
__global__ __launch_bounds__(256) void kD3()
{
    const int sb = blockIdx.y;
    const int m = blockIdx.x*256 + threadIdx.x;
    const float* Zb = g_Z + (size_t)sb*CC*MM + m;
    float s = 0.f;
#pragma unroll 8
    for (int c = 0; c < CC; ++c) s += Zb[(size_t)c*MM];
    g_aps[sb*MM + m] = s;
}

// ============ kE: blend + K/V update ============
__global__ __launch_bounds__(128) void kE(
    const float* __restrict__ emK, const float* __restrict__ emV,
    float* __restrict__ nK, float* __restrict__ nV)
{
    const int sb = blockIdx.y;
    const int m0 = blockIdx.x*32;
    const int tid = threadIdx.x, wid = tid >> 5, lane = tid & 31;
    __shared__ float cks[CC][DD];
    __shared__ float cvs[CC][DD];
    __shared__ float Zt[CC][32];
    for (int i = tid; i < CC*DD/4; i += 128) {
        int c = i >> 4, d4 = (i & 15) << 2;
        *(float4*)&cks[c][d4] = *(const float4*)&g_ckn[(sb*CC + c)*DD + d4];
        *(float4*)&cvs[c][d4] = *(const float4*)&g_cvv[(sb*CC + c)*DD + d4];
    }
    for (int i = tid; i < CC*32; i += 128) {
        int c = i >> 5, j = i & 31;
        Zt[c][j] = g_Z[((size_t)sb*CC + c)*MM + m0 + j];
    }
    __syncthreads();
#pragma unroll 1
    for (int p = 0; p < 8; ++p) {
        const int mj = p*4 + wid;
        const int m = m0 + mj;
        float aK0=0.f, aK1=0.f, aV0=0.f, aV1=0.f;
#pragma unroll
        for (int c = 0; c < CC; ++c) {
            float z = Zt[c][mj];
            aK0 += z*cks[c][lane];      aK1 += z*cks[c][lane+32];
            aV0 += z*cvs[c][lane];      aV1 += z*cvs[c][lane+32];
        }
        float aps = g_aps[sb*MM + m];
        float denom = fmaxf(aps, EPSV);
        float bk0 = aK0/denom, bk1 = aK1/denom;
        float nsq = bk0*bk0 + bk1*bk1;
#pragma unroll
        for (int o = 16; o; o >>= 1) nsq += __shfl_xor_sync(0xffffffffu, nsq, o);
        float nrm = fmaxf(sqrtf(nsq), EPSV);
        float uk0 = bk0/nrm, uk1 = bk1/nrm;
        float bv0 = aV0/denom, bv1 = aV1/denom;
        float ae = fminf(aps, 1.0f);
        bool upd = aps > EPSV;
        size_t base = ((size_t)sb*MM + m)*DD;
        float ek0 = emK[base+lane], ek1 = emK[base+lane+32];
        float ev0 = emV[base+lane], ev1 = emV[base+lane+32];
        nK[base+lane]    = upd ? (1.f-ae)*ek0 + ae*uk0 : ek0;
        nK[base+lane+32] = upd ? (1.f-ae)*ek1 + ae*uk1 : ek1;
        nV[base+lane]    = upd ? (1.f-ae)*ev0 + ae*bv0 : ev0;
        nV[base+lane+32] = upd ? (1.f-ae)*ev1 + ae*bv1 : ev1;
    }
}

// ============ kS1: per-(sb) strength total ============
__global__ __launch_bounds__(256) void kS1(
    const float* __restrict__ emS, const float* __restrict__ decay)
{
    const int sb = blockIdx.x, tid = threadIdx.x;
    __shared__ float red[256];
    const float dc = decay[sb];
    float loc = 0.f;
    for (int j = tid; j < MM; j += 256) {
        float pre = fminf(fmaxf(emS[sb*MM+j] + g_aps[sb*MM+j], 0.f), SMAXV) * dc;
        loc += pre;
    }
    red[tid] = loc; __syncthreads();
    for (int s2 = 128; s2; s2 >>= 1) { if (tid < s2) red[tid] += red[tid+s2]; __syncthreads(); }
    if (tid == 0) g_tot[sb] = red[0];
}

// ============ kS2: new_S, new_age ============
__global__ __launch_bounds__(256) void kS2(
    const float* __restrict__ emS, const float* __restrict__ emAge,
    const float* __restrict__ decay, float* __restrict__ nS, float* __restrict__ nAge)
{
    const int sb = blockIdx.y;
    const int m = blockIdx.x*256 + threadIdx.x;
    float aps = g_aps[sb*MM + m];
    float pre = fminf(fmaxf(emS[sb*MM+m] + aps, 0.f), SMAXV) * decay[sb];
    float scale = fminf(1.f, BUDGETV / (g_tot[sb] + EPSV));
    nS[sb*MM + m] = pre * scale;
    nAge[sb*MM + m] = emAge[sb*MM + m] * (1.f - aps);
}

extern "C" void kernel_launch(void* const* d_in, const int* in_sizes, int n_in,
                              void* d_out, int out_size)
{
    const float* q        = (const float*)d_in[0];
    const float* q_nov    = (const float*)d_in[1];
    const float* v_nov    = (const float*)d_in[2];
    const float* surprise = (const float*)d_in[3];
    const float* w_nov    = (const float*)d_in[4];
    const float* g_em_in  = (const float*)d_in[5];
    const float* tau      = (const float*)d_in[6];
    const float* decay    = (const float*)d_in[7];
    const float* ww       = (const float*)d_in[8];
    const float* em_K     = (const float*)d_in[9];
    const float* em_V     = (const float*)d_in[10];
    const float* em_S     = (const float*)d_in[11];
    const float* em_age   = (const float*)d_in[12];

    float* out  = (float*)d_out;                       // [4,1024,8,64]
    float* nK   = out + (size_t)BSZ*NQ*NB*DD;          // [4,8,2048,64]
    float* nV   = nK  + (size_t)SBT*MM*DD;
    float* nS   = nV  + (size_t)SBT*MM*DD;
    float* nAge = nS  + (size_t)SBT*MM;

    kA<<<dim3(NQ/32, NB, BSZ), 512>>>(q, q_nov, surprise, w_nov, em_K, em_V, em_S, out);
    kB<<<SBT, 256>>>(g_em_in);
    kC<<<dim3(CC, SBT), 32>>>(q_nov, v_nov);
    kD1<<<dim3(MM/256, SBT), 256>>>(em_K, em_S, ww, tau);
    kD2<<<SBT*CC, 256>>>();
    kD3<<<dim3(MM/256, SBT), 256>>>();
    kE<<<dim3(MM/32, SBT), 128>>>(em_K, em_V, nK, nV);
    kS1<<<SBT, 256>>>(em_S, decay);
    kS2<<<dim3(MM/256, SBT), 256>>>(em_S, em_age, decay, nS, nAge);
}

// round 3
// speedup vs baseline: 3.0523x; 3.0523x over previous
#include <cuda_runtime.h>
#include <math.h>

#define BSZ 4
#define NQ  1024
#define NB  8
#define DD  64
#define MM  2048
#define CC  64
#define QB  16
#define SBT (BSZ*NB)
#define NEGV (-1.0e9f)
#define EPSV 1e-8f
#define SMAXV 4.0f
#define BUDGETV 512.0f
#define FINF __int_as_float(0x7f800000)

// ---------- device scratch (no allocation allowed) ----------
__device__ float g_nov[SBT*NQ];
__device__ float g_cand_val[SBT*CC];
__device__ int   g_cand_idx[SBT*CC];
__device__ float g_coef[SBT*CC];
__device__ float g_ckn[SBT*CC*DD];
__device__ float g_cvv[SBT*CC*DD];
__device__ float g_Z[SBT*CC*MM];   // alpha, layout [sb][c][m]
__device__ float g_aps[SBT*MM];
__device__ float g_tot[SBT];

// 16 rounds of warp argmax-pop over per-lane ascending sorted lists.
// Returns vmax (1st) and thr (16th largest). Lane tie-break: lowest lane pops.
__device__ __forceinline__ void merge16(float* t, int lane, float& thr, float& vmax)
{
#pragma unroll 1
    for (int r = 0; r < 16; ++r) {
        float v = t[15]; int ln = lane;
#pragma unroll
        for (int o = 16; o; o >>= 1) {
            float v2 = __shfl_xor_sync(0xffffffffu, v, o);
            int   l2 = __shfl_xor_sync(0xffffffffu, ln, o);
            if (v2 > v || (v2 == v && l2 < ln)) { v = v2; ln = l2; }
        }
        if (r == 0) vmax = v;
        thr = v;
        if (lane == ln) {
#pragma unroll
            for (int i = 15; i > 0; --i) t[i] = t[i-1];
            t[0] = -FINF;
        }
    }
}

// ============ kA: read attention (exact top-16 softmax) + novelty ============
__global__ __launch_bounds__(256, 1) void kA(
    const float* __restrict__ q, const float* __restrict__ qn_,
    const float* __restrict__ surprise, const float* __restrict__ wnov,
    const float* __restrict__ emK, const float* __restrict__ emV,
    const float* __restrict__ emS, float* __restrict__ out)
{
    const int s = blockIdx.z, b = blockIdx.y, qt = blockIdx.x;
    const int sb = s*NB + b;
    const int tid = threadIdx.x, w = tid >> 5, lane = tid & 31;

    __shared__ float Ksm[64][68];
    __shared__ float Qs[QB][64];
    __shared__ float Qn[QB][64];
    __shared__ float actv[64];

    const int n0 = qt * QB;
    {   // 256 float4 per array, one per thread
        int r = tid >> 4, c4 = (tid & 15) << 2;
        int off = ((s*NQ + n0 + r)*NB + b)*DD + c4;
        *(float4*)&Qs[r][c4] = *(const float4*)&q[off];
        *(float4*)&Qn[r][c4] = *(const float4*)&qn_[off];
    }

    const int q0 = 2*w, q1 = 2*w + 1;
    float t0[16], t1[16];
#pragma unroll
    for (int i = 0; i < 16; ++i) { t0[i] = -FINF; t1[i] = -FINF; }
    float mx0 = -1.0f, mx1 = -1.0f;
    const float* Kb = emK + sb*MM*DD;
    const float* Sb = emS + sb*MM;

    // ---------------- pass 1: top-16 values + sim max ----------------
    for (int t = 0; t < MM/64; ++t) {
        __syncthreads();
        for (int i = tid; i < 1024; i += 256) {
            int r = i >> 4, c4 = (i & 15) << 2;
            *(float4*)&Ksm[r][c4] = *(const float4*)&Kb[(t*64 + r)*DD + c4];
        }
        if (tid < 64) actv[tid] = Sb[t*64 + tid];
        __syncthreads();
#pragma unroll
        for (int mo = 0; mo < 64; mo += 32) {
            const int ml = mo + lane;
            float a00 = 0.f, a01 = 0.f, a10 = 0.f, a11 = 0.f;
#pragma unroll
            for (int d4 = 0; d4 < 64; d4 += 4) {
                float4 kk = *(float4*)&Ksm[ml][d4];
                float4 x0 = *(float4*)&Qs[q0][d4];
                float4 y0 = *(float4*)&Qn[q0][d4];
                float4 x1 = *(float4*)&Qs[q1][d4];
                float4 y1 = *(float4*)&Qn[q1][d4];
                a00 = fmaf(x0.x,kk.x,a00); a00 = fmaf(x0.y,kk.y,a00);
                a00 = fmaf(x0.z,kk.z,a00); a00 = fmaf(x0.w,kk.w,a00);
                a10 = fmaf(x1.x,kk.x,a10); a10 = fmaf(x1.y,kk.y,a10);
                a10 = fmaf(x1.z,kk.z,a10); a10 = fmaf(x1.w,kk.w,a10);
                a01 = fmaf(y0.x,kk.x,a01); a01 = fmaf(y0.y,kk.y,a01);
                a01 = fmaf(y0.z,kk.z,a01); a01 = fmaf(y0.w,kk.w,a01);
                a11 = fmaf(y1.x,kk.x,a11); a11 = fmaf(y1.y,kk.y,a11);
                a11 = fmaf(y1.z,kk.z,a11); a11 = fmaf(y1.w,kk.w,a11);
            }
            const bool act = actv[ml] > 0.f;
            float sc0 = act ? a00 : NEGV;
            float sc1 = act ? a10 : NEGV;
            mx0 = fmaxf(mx0, act ? a01 : -1.0f);
            mx1 = fmaxf(mx1, act ? a11 : -1.0f);
            // branchless sorted insert (ascending, t[0]=min)
            t0[0] = fmaxf(t0[0], sc0);
#pragma unroll
            for (int i = 0; i < 15; ++i) {
                float lo = fminf(t0[i], t0[i+1]);
                float hi = fmaxf(t0[i], t0[i+1]);
                t0[i] = lo; t0[i+1] = hi;
            }
            t1[0] = fmaxf(t1[0], sc1);
#pragma unroll
            for (int i = 0; i < 15; ++i) {
                float lo = fminf(t1[i], t1[i+1]);
                float hi = fmaxf(t1[i], t1[i+1]);
                t1[i] = lo; t1[i+1] = hi;
            }
        }
    }

    float thr0, vm0, thr1, vm1;
    merge16(t0, lane, thr0, vm0);
    merge16(t1, lane, thr1, vm1);

    // ---------------- pass 2: exact rescore + weighted V gather ----------------
    float o00 = 0.f, o01 = 0.f, o10 = 0.f, o11 = 0.f;
    float ws0 = 0.f, ws1 = 0.f;
    const float* Vb = emV + sb*MM*DD;

    for (int t = 0; t < MM/64; ++t) {
        __syncthreads();
        for (int i = tid; i < 1024; i += 256) {
            int r = i >> 4, c4 = (i & 15) << 2;
            *(float4*)&Ksm[r][c4] = *(const float4*)&Kb[(t*64 + r)*DD + c4];
        }
        if (tid < 64) actv[tid] = Sb[t*64 + tid];
        __syncthreads();
#pragma unroll
        for (int mo = 0; mo < 64; mo += 32) {
            const int ml = mo + lane;
            float a00 = 0.f, a10 = 0.f;
#pragma unroll
            for (int d4 = 0; d4 < 64; d4 += 4) {
                float4 kk = *(float4*)&Ksm[ml][d4];
                float4 x0 = *(float4*)&Qs[q0][d4];
                float4 x1 = *(float4*)&Qs[q1][d4];
                a00 = fmaf(x0.x,kk.x,a00); a00 = fmaf(x0.y,kk.y,a00);
                a00 = fmaf(x0.z,kk.z,a00); a00 = fmaf(x0.w,kk.w,a00);
                a10 = fmaf(x1.x,kk.x,a10); a10 = fmaf(x1.y,kk.y,a10);
                a10 = fmaf(x1.z,kk.z,a10); a10 = fmaf(x1.w,kk.w,a10);
            }
            const bool act = actv[ml] > 0.f;
            float sc0 = act ? a00 : NEGV;
            float sc1 = act ? a10 : NEGV;
            float e0 = (sc0 >= thr0) ? __expf(sc0 - vm0) : 0.f;
            float e1 = (sc1 >= thr1) ? __expf(sc1 - vm1) : 0.f;
            ws0 += e0; ws1 += e1;
            unsigned h0 = __ballot_sync(0xffffffffu, e0 > 0.f);
            while (h0) {
                int l = __ffs(h0) - 1; h0 &= h0 - 1;
                float e = __shfl_sync(0xffffffffu, e0, l);
                int mi = t*64 + mo + l;
                o00 = fmaf(e, Vb[mi*DD + lane], o00);
                o01 = fmaf(e, Vb[mi*DD + lane + 32], o01);
            }
            unsigned h1 = __ballot_sync(0xffffffffu, e1 > 0.f);
            while (h1) {
                int l = __ffs(h1) - 1; h1 &= h1 - 1;
                float e = __shfl_sync(0xffffffffu, e1, l);
                int mi = t*64 + mo + l;
                o10 = fmaf(e, Vb[mi*DD + lane], o10);
                o11 = fmaf(e, Vb[mi*DD + lane + 32], o11);
            }
        }
    }

#pragma unroll
    for (int o = 16; o; o >>= 1) {
        ws0 += __shfl_xor_sync(0xffffffffu, ws0, o);
        ws1 += __shfl_xor_sync(0xffffffffu, ws1, o);
    }
    float inv0 = 1.f / ws0, inv1 = 1.f / ws1;
    int ob0 = ((s*NQ + n0 + q0)*NB + b)*DD;
    int ob1 = ((s*NQ + n0 + q1)*NB + b)*DD;
    out[ob0 + lane] = o00*inv0; out[ob0 + lane + 32] = o01*inv0;
    out[ob1 + lane] = o10*inv1; out[ob1 + lane + 32] = o11*inv1;

#pragma unroll
    for (int o = 16; o; o >>= 1) {
        mx0 = fmaxf(mx0, __shfl_xor_sync(0xffffffffu, mx0, o));
        mx1 = fmaxf(mx1, __shfl_xor_sync(0xffffffffu, mx1, o));
    }
    if (lane == 0) {
        float ms0 = fmaxf(mx0, 0.f), ms1 = fmaxf(mx1, 0.f);
        int off0 = (s*NQ + n0 + q0)*NB + b;
        int off1 = (s*NQ + n0 + q1)*NB + b;
        float w0 = wnov[off0], w1 = wnov[off1];
        g_nov[sb*NQ + n0 + q0] = w0*surprise[off0] + (1.f-w0)*(1.f-ms0);
        g_nov[sb*NQ + n0 + q1] = w1*surprise[off1] + (1.f-w1)*(1.f-ms1);
    }
}

// ============ kB: top-64 novelty per (s,b), coef ============
__global__ void kB(const float* __restrict__ g_em_in)
{
    const int sb = blockIdx.x, tid = threadIdx.x;
    __shared__ float vals[NQ];
    __shared__ float rv[8]; __shared__ int ri[8];
    __shared__ float svals[CC];
    __shared__ float ssum;
    for (int i = tid; i < NQ; i += 256) vals[i] = g_nov[sb*NQ + i];
    __syncthreads();
    for (int r = 0; r < CC; ++r) {
        float bv = -FINF; int bi = 0;
        for (int i = tid; i < NQ; i += 256) {
            float v = vals[i];
            if (v > bv) { bv = v; bi = i; }
        }
#pragma unroll
        for (int o = 16; o; o >>= 1) {
            float v2 = __shfl_xor_sync(0xffffffffu, bv, o);
            int   i2 = __shfl_xor_sync(0xffffffffu, bi, o);
            if (v2 > bv || (v2 == bv && i2 < bi)) { bv = v2; bi = i2; }
        }
        if ((tid & 31) == 0) { rv[tid>>5] = bv; ri[tid>>5] = bi; }
        __syncthreads();
        if (tid == 0) {
            for (int k = 1; k < 8; ++k)
                if (rv[k] > bv || (rv[k] == bv && ri[k] < bi)) { bv = rv[k]; bi = ri[k]; }
            g_cand_val[sb*CC + r] = bv;
            g_cand_idx[sb*CC + r] = bi;
            svals[r] = bv;
            vals[bi] = -FINF;
        }
        __syncthreads();
    }
    if (tid == 0) {
        float s = 0.f;
        for (int c = 0; c < CC; ++c) s += svals[c];
        ssum = s;
    }
    __syncthreads();
    if (tid < CC)
        g_coef[sb*CC + tid] = g_em_in[sb] * svals[tid] / (ssum + EPSV);
}

// ============ kC: gather candidates, unit-normalize K ============
__global__ void kC(const float* __restrict__ qn_, const float* __restrict__ vn_)
{
    const int c = blockIdx.x, sb = blockIdx.y;
    const int s = sb >> 3, b = sb & 7;
    const int lane = threadIdx.x;
    const int idx = g_cand_idx[sb*CC + c];
    const int base = ((s*NQ + idx)*NB + b)*DD;
    float k0 = qn_[base + lane], k1 = qn_[base + lane + 32];
    float v0 = vn_[base + lane], v1 = vn_[base + lane + 32];
    float nsq = k0*k0 + k1*k1;
#pragma unroll
    for (int o = 16; o; o >>= 1) nsq += __shfl_xor_sync(0xffffffffu, nsq, o);
    float nrm = fmaxf(sqrtf(nsq), EPSV);
    int ob = (sb*CC + c)*DD;
    g_ckn[ob + lane]      = k0/nrm;
    g_ckn[ob + lane + 32] = k1/nrm;
    g_cvv[ob + lane]      = v0;
    g_cvv[ob + lane + 32] = v1;
}

// ============ kD1: slot scores -> Z raw ============
__global__ __launch_bounds__(256) void kD1(
    const float* __restrict__ emK, const float* __restrict__ emS,
    const float* __restrict__ ww, const float* __restrict__ tau)
{
    const int sb = blockIdx.y;
    const int m = blockIdx.x*256 + threadIdx.x;
    __shared__ float ckns[CC][68];
    for (int i = threadIdx.x; i < 1024; i += 256) {
        int c = i >> 4, d4 = (i & 15) << 2;
        *(float4*)&ckns[c][d4] = *(const float4*)&g_ckn[(sb*CC + c)*DD + d4];
    }
    __syncthreads();
    float kreg[DD];
    const float* Kr = emK + (size_t)(sb*MM + m)*DD;
#pragma unroll
    for (int d4 = 0; d4 < DD; d4 += 4) *(float4*)&kreg[d4] = *(const float4*)&Kr[d4];
    const float bias = -ww[sb]*emS[sb*MM + m];
    const float invtau = 1.f / fmaxf(tau[sb], 0.01f);
    float* Zb = g_Z + (size_t)sb*CC*MM + m;
#pragma unroll 4
    for (int c = 0; c < CC; ++c) {
        float acc = 0.f;
#pragma unroll
        for (int d4 = 0; d4 < DD; d4 += 4) {
            float4 ck = *(float4*)&ckns[c][d4];
            acc += ck.x*kreg[d4] + ck.y*kreg[d4+1] + ck.z*kreg[d4+2] + ck.w*kreg[d4+3];
        }
        Zb[(size_t)c*MM] = (acc + bias) * invtau;
    }
}

// ============ kD2: softmax over m per (sb,c), scale by coef ============
__global__ __launch_bounds__(256) void kD2()
{
    const int row = blockIdx.x;          // sb*CC + c
    const int tid = threadIdx.x;
    float* zr = g_Z + (size_t)row*MM;
    __shared__ float buf[MM];
    __shared__ float red[256];
    float mx = -FINF;
    for (int j = tid; j < MM; j += 256) { float v = zr[j]; buf[j] = v; mx = fmaxf(mx, v); }
    red[tid] = mx; __syncthreads();
    for (int s2 = 128; s2; s2 >>= 1) { if (tid < s2) red[tid] = fmaxf(red[tid], red[tid+s2]); __syncthreads(); }
    mx = red[0]; __syncthreads();
    float sm = 0.f;
    for (int j = tid; j < MM; j += 256) { float e = __expf(buf[j] - mx); buf[j] = e; sm += e; }
    red[tid] = sm; __syncthreads();
    for (int s2 = 128; s2; s2 >>= 1) { if (tid < s2) red[tid] += red[tid+s2]; __syncthreads(); }
    const float scale = g_coef[row] / red[0];
    for (int j = tid; j < MM; j += 256) zr[j] = buf[j] * scale;
}

// ============ kD3: alpha_per_slot ============
__global__ __launch_bounds__(256) void kD3()
{
    const int sb = blockIdx.y;
    const int m = blockIdx.x*256 + threadIdx.x;
    const float* Zb = g_Z + (size_t)sb*CC*MM + m;
    float s = 0.f;
#pragma unroll 8
    for (int c = 0; c < CC; ++c) s += Zb[(size_t)c*MM];
    g_aps[sb*MM + m] = s;
}

// ============ kE: blend + K/V update ============
__global__ __launch_bounds__(128) void kE(
    const float* __restrict__ emK, const float* __restrict__ emV,
    float* __restrict__ nK, float* __restrict__ nV)
{
    const int sb = blockIdx.y;
    const int m0 = blockIdx.x*32;
    const int tid = threadIdx.x, wid = tid >> 5, lane = tid & 31;
    __shared__ float cks[CC][DD];
    __shared__ float cvs[CC][DD];
    __shared__ float Zt[CC][32];
    for (int i = tid; i < CC*DD/4; i += 128) {
        int c = i >> 4, d4 = (i & 15) << 2;
        *(float4*)&cks[c][d4] = *(const float4*)&g_ckn[(sb*CC + c)*DD + d4];
        *(float4*)&cvs[c][d4] = *(const float4*)&g_cvv[(sb*CC + c)*DD + d4];
    }
    for (int i = tid; i < CC*32; i += 128) {
        int c = i >> 5, j = i & 31;
        Zt[c][j] = g_Z[((size_t)sb*CC + c)*MM + m0 + j];
    }
    __syncthreads();
#pragma unroll 1
    for (int p = 0; p < 8; ++p) {
        const int mj = p*4 + wid;
        const int m = m0 + mj;
        float aK0=0.f, aK1=0.f, aV0=0.f, aV1=0.f;
#pragma unroll
        for (int c = 0; c < CC; ++c) {
            float z = Zt[c][mj];
            aK0 += z*cks[c][lane];      aK1 += z*cks[c][lane+32];
            aV0 += z*cvs[c][lane];      aV1 += z*cvs[c][lane+32];
        }
        float aps = g_aps[sb*MM + m];
        float denom = fmaxf(aps, EPSV);
        float bk0 = aK0/denom, bk1 = aK1/denom;
        float nsq = bk0*bk0 + bk1*bk1;
#pragma unroll
        for (int o = 16; o; o >>= 1) nsq += __shfl_xor_sync(0xffffffffu, nsq, o);
        float nrm = fmaxf(sqrtf(nsq), EPSV);
        float uk0 = bk0/nrm, uk1 = bk1/nrm;
        float bv0 = aV0/denom, bv1 = aV1/denom;
        float ae = fminf(aps, 1.0f);
        bool upd = aps > EPSV;
        size_t base = ((size_t)sb*MM + m)*DD;
        float ek0 = emK[base+lane], ek1 = emK[base+lane+32];
        float ev0 = emV[base+lane], ev1 = emV[base+lane+32];
        nK[base+lane]    = upd ? (1.f-ae)*ek0 + ae*uk0 : ek0;
        nK[base+lane+32] = upd ? (1.f-ae)*ek1 + ae*uk1 : ek1;
        nV[base+lane]    = upd ? (1.f-ae)*ev0 + ae*bv0 : ev0;
        nV[base+lane+32] = upd ? (1.f-ae)*ev1 + ae*bv1 : ev1;
    }
}

// ============ kS1: per-(sb) strength total ============
__global__ __launch_bounds__(256) void kS1(
    const float* __restrict__ emS, const float* __restrict__ decay)
{
    const int sb = blockIdx.x, tid = threadIdx.x;
    __shared__ float red[256];
    const float dc = decay[sb];
    float loc = 0.f;
    for (int j = tid; j < MM; j += 256) {
        float pre = fminf(fmaxf(emS[sb*MM+j] + g_aps[sb*MM+j], 0.f), SMAXV) * dc;
        loc += pre;
    }
    red[tid] = loc; __syncthreads();
    for (int s2 = 128; s2; s2 >>= 1) { if (tid < s2) red[tid] += red[tid+s2]; __syncthreads(); }
    if (tid == 0) g_tot[sb] = red[0];
}

// ============ kS2: new_S, new_age ============
__global__ __launch_bounds__(256) void kS2(
    const float* __restrict__ emS, const float* __restrict__ emAge,
    const float* __restrict__ decay, float* __restrict__ nS, float* __restrict__ nAge)
{
    const int sb = blockIdx.y;
    const int m = blockIdx.x*256 + threadIdx.x;
    float aps = g_aps[sb*MM + m];
    float pre = fminf(fmaxf(emS[sb*MM+m] + aps, 0.f), SMAXV) * decay[sb];
    float scale = fminf(1.f, BUDGETV / (g_tot[sb] + EPSV));
    nS[sb*MM + m] = pre * scale;
    nAge[sb*MM + m] = emAge[sb*MM + m] * (1.f - aps);
}

extern "C" void kernel_launch(void* const* d_in, const int* in_sizes, int n_in,
                              void* d_out, int out_size)
{
    const float* q        = (const float*)d_in[0];
    const float* q_nov    = (const float*)d_in[1];
    const float* v_nov    = (const float*)d_in[2];
    const float* surprise = (const float*)d_in[3];
    const float* w_nov    = (const float*)d_in[4];
    const float* g_em_in  = (const float*)d_in[5];
    const float* tau      = (const float*)d_in[6];
    const float* decay    = (const float*)d_in[7];
    const float* ww       = (const float*)d_in[8];
    const float* em_K     = (const float*)d_in[9];
    const float* em_V     = (const float*)d_in[10];
    const float* em_S     = (const float*)d_in[11];
    const float* em_age   = (const float*)d_in[12];

    float* out  = (float*)d_out;                       // [4,1024,8,64]
    float* nK   = out + (size_t)BSZ*NQ*NB*DD;          // [4,8,2048,64]
    float* nV   = nK  + (size_t)SBT*MM*DD;
    float* nS   = nV  + (size_t)SBT*MM*DD;
    float* nAge = nS  + (size_t)SBT*MM;

    kA<<<dim3(NQ/QB, NB, BSZ), 256>>>(q, q_nov, surprise, w_nov, em_K, em_V, em_S, out);
    kB<<<SBT, 256>>>(g_em_in);
    kC<<<dim3(CC, SBT), 32>>>(q_nov, v_nov);
    kD1<<<dim3(MM/256, SBT), 256>>>(em_K, em_S, ww, tau);
    kD2<<<SBT*CC, 256>>>();
    kD3<<<dim3(MM/256, SBT), 256>>>();
    kE<<<dim3(MM/32, SBT), 128>>>(em_K, em_V, nK, nV);
    kS1<<<SBT, 256>>>(em_S, decay);
    kS2<<<dim3(MM/256, SBT), 256>>>(em_S, em_age, decay, nS, nAge);
}